// round 13
// baseline (speedup 1.0000x reference)
#include <cuda_runtime.h>
#include <math.h>

#define B_ 8
#define L_ 1024
#define D_ 256
#define U_ 256
#define NCHUNK 8
#define CHUNK 128

typedef unsigned long long ull;

// ---------------- scratch (device globals; no allocation allowed) ----------
__device__ float g_EW[D_ * U_];          // E @ Wx            (256 KB)
__device__ float g_rnorm[B_ * L_];       // 1/max(rowsum,eps)
__device__ float g_tp0[B_ * L_ * U_];    // seq[:,0:128]@EW[0:128]   (unscaled)
__device__ float g_tp1[B_ * L_ * U_];    // seq[:,128:256]@EW[128:256]
__device__ float g_xp0[B_ * L_ * U_];    // G^T @ t partials  (8 MB each)
__device__ float g_xp1[B_ * L_ * U_];
__device__ float g_xp2[B_ * L_ * U_];
__device__ float g_xp3[B_ * L_ * U_];
__device__ int g_flags[B_][NCHUNK];      // xproj chunk flags (count 8)
__device__ int g_tfl[B_ * 4];            // t ready per (b,ks) (count 8)
__device__ int g_nfl[B_ * 4];            // rn ready per (b,ks) (count 1)

// ---------------- packed f32x2 helpers (sm_103a) ----------------------------
__device__ __forceinline__ ull pk2(float lo, float hi) {
    ull r; asm("mov.b64 %0,{%1,%2};" : "=l"(r) : "f"(lo), "f"(hi)); return r;
}
__device__ __forceinline__ void ffma2(ull& d, ull a, ull b) {
    asm("fma.rn.f32x2 %0,%1,%2,%0;" : "+l"(d) : "l"(a), "l"(b));
}
__device__ __forceinline__ float2 up2(ull a) {
    float lo, hi; asm("mov.b64 {%0,%1},%2;" : "=f"(lo), "=f"(hi) : "l"(a));
    float2 r; r.x = lo; r.y = hi; return r;
}
// tanh(z) = 1 - 2/(1+exp(2z)) via MUFU (rel err ~1e-6; validated R3-R12)
__device__ __forceinline__ float fast_tanh(float z) {
    float t2 = z * 2.885390081777927f;  // 2*log2(e)
    float ex; asm("ex2.approx.f32 %0,%1;" : "=f"(ex) : "f"(t2));
    float den = ex + 1.0f;
    float rc; asm("rcp.approx.f32 %0,%1;" : "=f"(rc) : "f"(den));
    return fmaf(-2.0f, rc, 1.0f);
}

// ---------------- 1) GEMM NN standalone (EW = E @ Wx; also zeroes flags) ----
__global__ __launch_bounds__(256) void gemm_nn(const float* __restrict__ A,
                                               const float* __restrict__ Bm,
                                               float* __restrict__ C, int K,
                                               const float* __restrict__ rowscale) {
    __shared__ float As[2][16][128];
    __shared__ float Bs[2][16][128];
    const int N = 256;
    const int m0 = blockIdx.y * 128, n0 = blockIdx.x * 128;
    const int t = threadIdx.x;
    const int tx = t & 15, ty = t >> 4;

    // flag zeroing piggybacked on block (0,0): done before the fused kernel
    // launches (stream order), re-done on every graph replay.
    if (blockIdx.x == 0 && blockIdx.y == 0) {
        if (t < B_ * NCHUNK) ((int*)g_flags)[t] = 0;
        if (t < B_ * 4) { g_tfl[t] = 0; g_nfl[t] = 0; }
    }

    ull acc[8][4];
#pragma unroll
    for (int i = 0; i < 8; i++)
#pragma unroll
        for (int j = 0; j < 4; j++) acc[i][j] = 0ull;

    int am[2], akg[2], bkk[2], bng[2];
#pragma unroll
    for (int i = 0; i < 2; i++) {
        int f4 = t + i * 256;
        am[i] = f4 >> 2; akg[i] = f4 & 3;
        bkk[i] = f4 >> 5; bng[i] = f4 & 31;
    }

    float4 ra[2], rb[2];
#pragma unroll
    for (int i = 0; i < 2; i++) {
        ra[i] = *(const float4*)(A + (size_t)(m0 + am[i]) * K + akg[i] * 4);
        rb[i] = *(const float4*)(Bm + (size_t)bkk[i] * N + n0 + bng[i] * 4);
    }

    int cur = 0;
    for (int k0 = 0; k0 < K; k0 += 16) {
#pragma unroll
        for (int i = 0; i < 2; i++) {
            As[cur][akg[i] * 4 + 0][am[i]] = ra[i].x;
            As[cur][akg[i] * 4 + 1][am[i]] = ra[i].y;
            As[cur][akg[i] * 4 + 2][am[i]] = ra[i].z;
            As[cur][akg[i] * 4 + 3][am[i]] = ra[i].w;
            *(float4*)&Bs[cur][bkk[i]][bng[i] * 4] = rb[i];
        }
        __syncthreads();
        if (k0 + 16 < K) {
#pragma unroll
            for (int i = 0; i < 2; i++) {
                ra[i] = *(const float4*)(A + (size_t)(m0 + am[i]) * K + k0 + 16 + akg[i] * 4);
                rb[i] = *(const float4*)(Bm + (size_t)(k0 + 16 + bkk[i]) * N + n0 + bng[i] * 4);
            }
        }
#pragma unroll
        for (int kk = 0; kk < 16; kk++) {
            float4 a0 = *(float4*)&As[cur][kk][ty * 8];
            float4 a1 = *(float4*)&As[cur][kk][ty * 8 + 4];
            float4 b0 = *(float4*)&Bs[cur][kk][tx * 8];
            float4 b1 = *(float4*)&Bs[cur][kk][tx * 8 + 4];
            ull bp0 = pk2(b0.x, b0.y), bp1 = pk2(b0.z, b0.w);
            ull bp2 = pk2(b1.x, b1.y), bp3 = pk2(b1.z, b1.w);
            float av[8] = {a0.x, a0.y, a0.z, a0.w, a1.x, a1.y, a1.z, a1.w};
#pragma unroll
            for (int i = 0; i < 8; i++) {
                ull ad = pk2(av[i], av[i]);
                ffma2(acc[i][0], ad, bp0);
                ffma2(acc[i][1], ad, bp1);
                ffma2(acc[i][2], ad, bp2);
                ffma2(acc[i][3], ad, bp3);
            }
        }
        cur ^= 1;
    }
#pragma unroll
    for (int i = 0; i < 8; i++) {
        int row = m0 + ty * 8 + i;
        float sc = rowscale ? rowscale[row] : 1.f;
        float2 v0 = up2(acc[i][0]), v1 = up2(acc[i][1]);
        float2 v2 = up2(acc[i][2]), v3 = up2(acc[i][3]);
        float4 o0 = make_float4(v0.x * sc, v0.y * sc, v1.x * sc, v1.y * sc);
        float4 o1 = make_float4(v2.x * sc, v2.y * sc, v3.x * sc, v3.y * sc);
        *(float4*)(C + (size_t)row * N + n0 + tx * 8) = o0;
        *(float4*)(C + (size_t)row * N + n0 + tx * 8 + 4) = o1;
    }
}

// ---------------- fused pipeline kernel --------------------------------------
// blockIdx roles:
//   [0, 8)     scan CTAs (one per batch)      — waits on g_flags chunks
//   [8, 40)    norm CTAs (b*4+ks)             — produces g_rnorm + g_nfl
//   [40, 296)  t' CTAs (seq@EW K-split 2)     — produces tp0/tp1 + g_tfl
//   [296, 808) gemm_tn CTAs (K-split 4)       — waits tfl+nfl, produces xq*
#define RF_PAIRS 26
#define SM_PAIRS 6
#define WS2_ELEMS (SM_PAIRS * 2 * 256)           // 3072 ulonglong2 = 48 KB
#define OFF_PART (WS2_ELEMS * 16)
#define OFF_HB (OFF_PART + 2 * 1024 * 4)         // part double-buffered (8 KB)
#define SCAN_SMEM_BYTES (OFF_HB + 2 * 256 * 4)   // 48K + 8K + 2K = 58 KB

__global__ __launch_bounds__(256) void fused_kernel(
    const float* __restrict__ graph, const float* __restrict__ seq,
    const float* __restrict__ ewp,
    const float* __restrict__ Wh, const float* __restrict__ bias,
    float* __restrict__ rn,
    float* __restrict__ tq0, float* __restrict__ tq1,
    float* __restrict__ xq0, float* __restrict__ xq1,
    float* __restrict__ xq2, float* __restrict__ xq3,
    float* __restrict__ out) {
    extern __shared__ unsigned char smraw[];
    const int tid = threadIdx.x;
    const int bid = blockIdx.x;

    if (bid >= 8 && bid < 40) {
        // ================= norm role: rows [ks*256, +256) of batch b ========
        const int nb = bid - 8;
        const int b = nb >> 2, ks4 = nb & 3;
        const int w = tid >> 5, l = tid & 31;
        const float* gb = graph + (size_t)b * L_ * L_ + (size_t)ks4 * 256 * L_;
        for (int r = w; r < 256; r += 8) {
            const float4* row = (const float4*)(gb + (size_t)r * L_);
            float s = 0.f;
#pragma unroll
            for (int i = l; i < L_ / 4; i += 32) {
                float4 v = row[i];
                s += (v.x + v.y) + (v.z + v.w);
            }
#pragma unroll
            for (int o = 16; o; o >>= 1) s += __shfl_xor_sync(0xffffffffu, s, o);
            if (l == 0) rn[b * L_ + ks4 * 256 + r] = 1.f / fmaxf(s, 1e-7f);
        }
        __threadfence();
        __syncthreads();
        if (tid == 0) atomicAdd(&g_nfl[nb], 1);
        return;
    }

    if (bid >= 40 && bid < 296) {
        // ================= t' role: seq @ EW, K-split 2, unscaled ===========
        float (*As)[16][128] = (float (*)[16][128])smraw;
        float (*Bs)[16][128] = (float (*)[16][128])(smraw + 2 * 16 * 128 * 4);
        const int gid = bid - 40;
        const int nt = gid & 1, mt = (gid >> 1) & 63, kz = gid >> 7;
        const int K = 256, N = 256;
        const int m0 = mt * 128, n0 = nt * 128;
        const int kbeg = kz * 128, kend = kbeg + 128;
        float* C = kz ? tq1 : tq0;
        const int tx = tid & 15, ty = tid >> 4;

        ull acc[8][4];
#pragma unroll
        for (int i = 0; i < 8; i++)
#pragma unroll
            for (int j = 0; j < 4; j++) acc[i][j] = 0ull;

        int am[2], akg[2], bkk[2], bng[2];
#pragma unroll
        for (int i = 0; i < 2; i++) {
            int f4 = tid + i * 256;
            am[i] = f4 >> 2; akg[i] = f4 & 3;
            bkk[i] = f4 >> 5; bng[i] = f4 & 31;
        }

        float4 ra[2], rb[2];
#pragma unroll
        for (int i = 0; i < 2; i++) {
            ra[i] = *(const float4*)(seq + (size_t)(m0 + am[i]) * K + kbeg + akg[i] * 4);
            rb[i] = *(const float4*)(ewp + (size_t)(kbeg + bkk[i]) * N + n0 + bng[i] * 4);
        }

        int cur = 0;
        for (int k0 = kbeg; k0 < kend; k0 += 16) {
#pragma unroll
            for (int i = 0; i < 2; i++) {
                As[cur][akg[i] * 4 + 0][am[i]] = ra[i].x;
                As[cur][akg[i] * 4 + 1][am[i]] = ra[i].y;
                As[cur][akg[i] * 4 + 2][am[i]] = ra[i].z;
                As[cur][akg[i] * 4 + 3][am[i]] = ra[i].w;
                *(float4*)&Bs[cur][bkk[i]][bng[i] * 4] = rb[i];
            }
            __syncthreads();
            if (k0 + 16 < kend) {
#pragma unroll
                for (int i = 0; i < 2; i++) {
                    ra[i] = *(const float4*)(seq + (size_t)(m0 + am[i]) * K + k0 + 16 + akg[i] * 4);
                    rb[i] = *(const float4*)(ewp + (size_t)(k0 + 16 + bkk[i]) * N + n0 + bng[i] * 4);
                }
            }
#pragma unroll
            for (int kk = 0; kk < 16; kk++) {
                float4 a0 = *(float4*)&As[cur][kk][ty * 8];
                float4 a1 = *(float4*)&As[cur][kk][ty * 8 + 4];
                float4 b0 = *(float4*)&Bs[cur][kk][tx * 8];
                float4 b1 = *(float4*)&Bs[cur][kk][tx * 8 + 4];
                ull bp0 = pk2(b0.x, b0.y), bp1 = pk2(b0.z, b0.w);
                ull bp2 = pk2(b1.x, b1.y), bp3 = pk2(b1.z, b1.w);
                float av[8] = {a0.x, a0.y, a0.z, a0.w, a1.x, a1.y, a1.z, a1.w};
#pragma unroll
                for (int i = 0; i < 8; i++) {
                    ull ad = pk2(av[i], av[i]);
                    ffma2(acc[i][0], ad, bp0);
                    ffma2(acc[i][1], ad, bp1);
                    ffma2(acc[i][2], ad, bp2);
                    ffma2(acc[i][3], ad, bp3);
                }
            }
            cur ^= 1;
        }
#pragma unroll
        for (int i = 0; i < 8; i++) {
            int row = m0 + ty * 8 + i;
            float2 v0 = up2(acc[i][0]), v1 = up2(acc[i][1]);
            float2 v2 = up2(acc[i][2]), v3 = up2(acc[i][3]);
            float4 o0 = make_float4(v0.x, v0.y, v1.x, v1.y);
            float4 o1 = make_float4(v2.x, v2.y, v3.x, v3.y);
            *(float4*)(C + (size_t)row * N + n0 + tx * 8) = o0;
            *(float4*)(C + (size_t)row * N + n0 + tx * 8 + 4) = o1;
        }
        __threadfence();
        __syncthreads();
        if (tid == 0) atomicAdd(&g_tfl[(mt >> 3) * 4 + ((mt & 7) >> 1)], 1);
        return;
    }

    if (bid >= 296) {
        // ================= gemm_tn role (K-split 4, rn applied to A) ========
        float (*As)[16][128] = (float (*)[16][128])smraw;
        float (*Bs)[16][128] = (float (*)[16][128])(smraw + 2 * 16 * 128 * 4);
        const int gid = bid - 296;
        const int nt = gid & 1, bks = (gid >> 1) & 31, mchunk = gid >> 6;
        const int b = bks >> 2, ks = bks & 3;
        const int kbeg = ks * (L_ / 4), kend = kbeg + (L_ / 4);
        const int N = 256, lda = L_;
        const float* Ab = graph + (size_t)b * L_ * L_;
        const float* Bb0 = tq0 + (size_t)b * L_ * U_;
        const float* Bb1 = tq1 + (size_t)b * L_ * U_;
        const float* rnb = rn + (size_t)b * L_;
        float* Cs = (ks == 0) ? xq0 : (ks == 1) ? xq1 : (ks == 2) ? xq2 : xq3;
        float* C = Cs + (size_t)b * L_ * U_;
        const int m0 = mchunk * 128, n0 = nt * 128;
        const int tx = tid & 15, ty = tid >> 4;

        {
            volatile int* tf = &g_tfl[b * 4 + ks];
            volatile int* nf = &g_nfl[b * 4 + ks];
            if (tid == 0) {
                while (*tf < 8) { }
                while (*nf < 1) { }
            }
            __syncthreads();
            __threadfence();
        }

        ull acc[8][4];
#pragma unroll
        for (int i = 0; i < 8; i++)
#pragma unroll
            for (int j = 0; j < 4; j++) acc[i][j] = 0ull;

        int kk_[2], g_[2];
#pragma unroll
        for (int i = 0; i < 2; i++) {
            int f4 = tid + i * 256;
            kk_[i] = f4 >> 5; g_[i] = f4 & 31;
        }

        float4 ra[2], rb0[2], rb1[2];
        float rsc[2];
#pragma unroll
        for (int i = 0; i < 2; i++) {
            size_t ko = (size_t)(kbeg + kk_[i]);
            ra[i] = *(const float4*)(Ab + ko * lda + m0 + g_[i] * 4);
            rb0[i] = *(const float4*)(Bb0 + ko * N + n0 + g_[i] * 4);
            rb1[i] = *(const float4*)(Bb1 + ko * N + n0 + g_[i] * 4);
            rsc[i] = rnb[ko];
        }

        int cur = 0;
        for (int k0 = kbeg; k0 < kend; k0 += 16) {
#pragma unroll
            for (int i = 0; i < 2; i++) {
                float r = rsc[i];
                float4 sa = make_float4(ra[i].x * r, ra[i].y * r,
                                        ra[i].z * r, ra[i].w * r);
                *(float4*)&As[cur][kk_[i]][g_[i] * 4] = sa;
                float4 s = make_float4(rb0[i].x + rb1[i].x, rb0[i].y + rb1[i].y,
                                       rb0[i].z + rb1[i].z, rb0[i].w + rb1[i].w);
                *(float4*)&Bs[cur][kk_[i]][g_[i] * 4] = s;
            }
            __syncthreads();
            if (k0 + 16 < kend) {
#pragma unroll
                for (int i = 0; i < 2; i++) {
                    size_t ko = (size_t)(k0 + 16 + kk_[i]);
                    ra[i] = *(const float4*)(Ab + ko * lda + m0 + g_[i] * 4);
                    rb0[i] = *(const float4*)(Bb0 + ko * N + n0 + g_[i] * 4);
                    rb1[i] = *(const float4*)(Bb1 + ko * N + n0 + g_[i] * 4);
                    rsc[i] = rnb[ko];
                }
            }
#pragma unroll
            for (int kk = 0; kk < 16; kk++) {
                float4 a0 = *(float4*)&As[cur][kk][ty * 8];
                float4 a1 = *(float4*)&As[cur][kk][ty * 8 + 4];
                float4 b0 = *(float4*)&Bs[cur][kk][tx * 8];
                float4 b1 = *(float4*)&Bs[cur][kk][tx * 8 + 4];
                ull bp0 = pk2(b0.x, b0.y), bp1 = pk2(b0.z, b0.w);
                ull bp2 = pk2(b1.x, b1.y), bp3 = pk2(b1.z, b1.w);
                float av[8] = {a0.x, a0.y, a0.z, a0.w, a1.x, a1.y, a1.z, a1.w};
#pragma unroll
                for (int i = 0; i < 8; i++) {
                    ull ad = pk2(av[i], av[i]);
                    ffma2(acc[i][0], ad, bp0);
                    ffma2(acc[i][1], ad, bp1);
                    ffma2(acc[i][2], ad, bp2);
                    ffma2(acc[i][3], ad, bp3);
                }
            }
            cur ^= 1;
        }
#pragma unroll
        for (int i = 0; i < 8; i++) {
            int row = m0 + ty * 8 + i;
            float2 v0 = up2(acc[i][0]), v1 = up2(acc[i][1]);
            float2 v2 = up2(acc[i][2]), v3 = up2(acc[i][3]);
            float4 o0 = make_float4(v0.x, v0.y, v1.x, v1.y);
            float4 o1 = make_float4(v2.x, v2.y, v3.x, v3.y);
            *(float4*)(C + (size_t)row * N + n0 + tx * 8) = o0;
            *(float4*)(C + (size_t)row * N + n0 + tx * 8 + 4) = o1;
        }
        __threadfence();
        __syncthreads();
        if (tid == 0) atomicAdd(&g_flags[b][mchunk], 1);
        return;
    }

    // ================= scan role: global BAR1 + pair-local named BAR2 =======
    ulonglong2* ws2 = (ulonglong2*)smraw;               // 48 KB weights
    float* part = (float*)(smraw + OFF_PART);           // 8 KB (double buf)
    float* hbuf = (float*)(smraw + OFF_HB);             // 2 KB h (double buf)

    const int b = bid;
    const int w = tid >> 5, l = tid & 31;
    const int ks = w >> 1, oh = w & 1;
    const int u0 = oh * 128 + l * 4;
    const int pairbar = 1 + (tid >> 6);                 // named barrier 1..4

    for (int idx = tid; idx < WS2_ELEMS; idx += 256) {
        int e = idx >> 8;
        int r = idx & 255;
        int ps = e >> 1, jp = e & 1;
        int wf = r >> 5, lf = r & 31;
        int ksf = wf >> 1, ohf = wf & 1;
        int uf = ohf * 128 + lf * 4 + 2 * jp;
        int kf = ksf * 64 + 2 * (RF_PAIRS + ps);
        ulonglong2 v;
        v.x = pk2(Wh[kf * U_ + uf], Wh[(kf + 1) * U_ + uf]);
        v.y = pk2(Wh[kf * U_ + uf + 1], Wh[(kf + 1) * U_ + uf + 1]);
        ws2[idx] = v;
    }

    ull wreg[4][RF_PAIRS];
#pragma unroll
    for (int j = 0; j < 4; j++)
#pragma unroll
        for (int p = 0; p < RF_PAIRS; p++) {
            int k = ks * 64 + 2 * p;
            wreg[j][p] = pk2(Wh[k * U_ + u0 + j], Wh[(k + 1) * U_ + u0 + j]);
        }

    hbuf[tid] = 0.f;
    hbuf[256 + tid] = 0.f;
    const float bv = bias[tid];
    __syncthreads();

    const float* xp0 = xq0 + (size_t)b * L_ * U_ + tid;
    const float* xp1 = xq1 + (size_t)b * L_ * U_ + tid;
    const float* xp2 = xq2 + (size_t)b * L_ * U_ + tid;
    const float* xp3 = xq3 + (size_t)b * L_ * U_ + tid;
    float* op = out + (size_t)b * L_ * U_ + tid;
    int cur = 0;

    const ulonglong2* wp = ws2 + tid;
    volatile int* flagp = &g_flags[b][0];

    for (int c = 0; c < NCHUNK; c++) {
        if (tid == 0) {
            while (flagp[c] < 8) { }
        }
        __syncthreads();
        __threadfence();  // acquire: pair with producers' release fences

        for (int si = 0; si < CHUNK; si++) {
            int s = c * CHUNK + si;
            size_t xo = (size_t)s * U_;
            float xa = xp0[xo], xb = xp1[xo], xc = xp2[xo], xd = xp3[xo];
            float* pb = part + (si & 1) * 1024;   // step-parity buffer

            const ulonglong2* hp2 = (const ulonglong2*)(hbuf + cur * 256 + ks * 64);
            ull a0 = 0ull, a1 = 0ull, a2 = 0ull, a3 = 0ull;
            // SMEM-weight FMAs first (R9 win), LDS.128 packed (R12)
#pragma unroll
            for (int qq = 0; qq < 3; qq++) { // pairs 26..31
                ulonglong2 hv = hp2[13 + qq];
                int ps0 = 2 * qq, ps1 = 2 * qq + 1;
                ulonglong2 W0a = wp[(ps0 * 2 + 0) * 256];
                ulonglong2 W0b = wp[(ps0 * 2 + 1) * 256];
                ffma2(a0, hv.x, W0a.x);
                ffma2(a1, hv.x, W0a.y);
                ffma2(a2, hv.x, W0b.x);
                ffma2(a3, hv.x, W0b.y);
                ulonglong2 W1a = wp[(ps1 * 2 + 0) * 256];
                ulonglong2 W1b = wp[(ps1 * 2 + 1) * 256];
                ffma2(a0, hv.y, W1a.x);
                ffma2(a1, hv.y, W1a.y);
                ffma2(a2, hv.y, W1b.x);
                ffma2(a3, hv.y, W1b.y);
            }
#pragma unroll
            for (int q = 0; q < 13; q++) {   // pairs 0..25 (RF)
                ulonglong2 hv = hp2[q];
                ffma2(a0, hv.x, wreg[0][2 * q]);
                ffma2(a1, hv.x, wreg[1][2 * q]);
                ffma2(a2, hv.x, wreg[2][2 * q]);
                ffma2(a3, hv.x, wreg[3][2 * q]);
                ffma2(a0, hv.y, wreg[0][2 * q + 1]);
                ffma2(a1, hv.y, wreg[1][2 * q + 1]);
                ffma2(a2, hv.y, wreg[2][2 * q + 1]);
                ffma2(a3, hv.y, wreg[3][2 * q + 1]);
            }
            float2 v0 = up2(a0), v1 = up2(a1), v2 = up2(a2), v3 = up2(a3);
            float4 pr = make_float4(v0.x + v0.y, v1.x + v1.y,
                                    v2.x + v2.y, v3.x + v3.y);
            float xv = ((xa + xb) + (xc + xd)) + bv;
            *(float4*)&pb[ks * 256 + u0] = pr;
            __syncthreads();   // global BAR1: part exchange is all-to-all

            float z = pb[tid] + pb[256 + tid] + pb[512 + tid] +
                      pb[768 + tid] + xv;
            float h = fast_tanh(z);
            hbuf[(cur ^ 1) * 256 + tid] = h;
            op[xo] = h;
            cur ^= 1;
            // pair-local BAR2: h recurrence is closed within warp pairs
            // {2ks, 2ks+1}; part WAR across pairs is closed by the parity
            // double-buffer + next step's global BAR1.
            asm volatile("bar.sync %0, %1;" :: "r"(pairbar), "r"(64) : "memory");
        }
    }
}

// ---------------- launch --------------------------------------------------
extern "C" void kernel_launch(void* const* d_in, const int* in_sizes, int n_in,
                              void* d_out, int out_size) {
    const float* seq = (const float*)d_in[0];    // (8,1024,256)
    const float* graph = (const float*)d_in[1];  // (8,1024,1024)
    const float* E = (const float*)d_in[2];      // (256,256)
    const float* Wx = (const float*)d_in[3];     // (256,256)
    const float* Wh = (const float*)d_in[4];     // (256,256)
    const float* bias = (const float*)d_in[5];   // (256,)
    float* out = (float*)d_out;                  // (8,1024,256)

    float *ew, *rn, *t0, *t1, *x0, *x1, *x2, *x3;
    cudaGetSymbolAddress((void**)&ew, g_EW);
    cudaGetSymbolAddress((void**)&rn, g_rnorm);
    cudaGetSymbolAddress((void**)&t0, g_tp0);
    cudaGetSymbolAddress((void**)&t1, g_tp1);
    cudaGetSymbolAddress((void**)&x0, g_xp0);
    cudaGetSymbolAddress((void**)&x1, g_xp1);
    cudaGetSymbolAddress((void**)&x2, g_xp2);
    cudaGetSymbolAddress((void**)&x3, g_xp3);

    // EW = E @ Wx (also zeroes all pipeline flags in block (0,0))
    gemm_nn<<<dim3(2, 2), 256>>>(E, Wx, ew, 256, nullptr);
    // everything else: one fused pipeline kernel
    cudaFuncSetAttribute(fused_kernel, cudaFuncAttributeMaxDynamicSharedMemorySize,
                         SCAN_SMEM_BYTES);
    fused_kernel<<<808, 256, SCAN_SMEM_BYTES>>>(graph, seq, ew, Wh, bias, rn,
                                                t0, t1, x0, x1, x2, x3, out);
}

// round 14
// speedup vs baseline: 1.2568x; 1.2568x over previous
#include <cuda_runtime.h>
#include <math.h>

#define B_ 8
#define L_ 1024
#define D_ 256
#define U_ 256
#define NCHUNK 8
#define CHUNK 128

typedef unsigned long long ull;

// ---------------- scratch (device globals; no allocation allowed) ----------
__device__ float g_EW[D_ * U_];          // E @ Wx            (256 KB)
__device__ float g_rnorm[B_ * L_];       // 1/max(rowsum,eps)
__device__ float g_tp0[B_ * L_ * U_];    // seq[:,0:128]@EW[0:128]   (unscaled)
__device__ float g_tp1[B_ * L_ * U_];    // seq[:,128:256]@EW[128:256]
__device__ float g_xp0[B_ * L_ * U_];    // G^T @ t partials  (8 MB each)
__device__ float g_xp1[B_ * L_ * U_];
__device__ float g_xp2[B_ * L_ * U_];
__device__ float g_xp3[B_ * L_ * U_];
__device__ int g_flags[B_][NCHUNK];      // xproj chunk flags (count 8)
__device__ int g_tfl[B_ * 4];            // t ready per (b,ks) (count 8)
__device__ int g_nfl[B_ * 4];            // rn ready per (b,ks) (count 1)

// ---------------- packed f32x2 helpers (sm_103a) ----------------------------
__device__ __forceinline__ ull pk2(float lo, float hi) {
    ull r; asm("mov.b64 %0,{%1,%2};" : "=l"(r) : "f"(lo), "f"(hi)); return r;
}
__device__ __forceinline__ void ffma2(ull& d, ull a, ull b) {
    asm("fma.rn.f32x2 %0,%1,%2,%0;" : "+l"(d) : "l"(a), "l"(b));
}
__device__ __forceinline__ float2 up2(ull a) {
    float lo, hi; asm("mov.b64 {%0,%1},%2;" : "=f"(lo), "=f"(hi) : "l"(a));
    float2 r; r.x = lo; r.y = hi; return r;
}
// tanh(z) = 1 - 2/(1+exp(2z)) via MUFU (rel err ~1e-6; validated R3-R13)
__device__ __forceinline__ float fast_tanh(float z) {
    float t2 = z * 2.885390081777927f;  // 2*log2(e)
    float ex; asm("ex2.approx.f32 %0,%1;" : "=f"(ex) : "f"(t2));
    float den = ex + 1.0f;
    float rc; asm("rcp.approx.f32 %0,%1;" : "=f"(rc) : "f"(den));
    return fmaf(-2.0f, rc, 1.0f);
}

// ---------------- 1) GEMM NN standalone (EW = E @ Wx; also zeroes flags) ----
__global__ __launch_bounds__(256) void gemm_nn(const float* __restrict__ A,
                                               const float* __restrict__ Bm,
                                               float* __restrict__ C, int K,
                                               const float* __restrict__ rowscale) {
    __shared__ float As[2][16][128];
    __shared__ float Bs[2][16][128];
    const int N = 256;
    const int m0 = blockIdx.y * 128, n0 = blockIdx.x * 128;
    const int t = threadIdx.x;
    const int tx = t & 15, ty = t >> 4;

    // flag zeroing piggybacked on block (0,0): same-stream kernels serialize,
    // so all flags are zero before fused_kernel starts (every graph replay).
    if (blockIdx.x == 0 && blockIdx.y == 0) {
        if (t < B_ * NCHUNK) ((int*)g_flags)[t] = 0;
        if (t < B_ * 4) { g_tfl[t] = 0; g_nfl[t] = 0; }
    }

    ull acc[8][4];
#pragma unroll
    for (int i = 0; i < 8; i++)
#pragma unroll
        for (int j = 0; j < 4; j++) acc[i][j] = 0ull;

    int am[2], akg[2], bkk[2], bng[2];
#pragma unroll
    for (int i = 0; i < 2; i++) {
        int f4 = t + i * 256;
        am[i] = f4 >> 2; akg[i] = f4 & 3;
        bkk[i] = f4 >> 5; bng[i] = f4 & 31;
    }

    float4 ra[2], rb[2];
#pragma unroll
    for (int i = 0; i < 2; i++) {
        ra[i] = *(const float4*)(A + (size_t)(m0 + am[i]) * K + akg[i] * 4);
        rb[i] = *(const float4*)(Bm + (size_t)bkk[i] * N + n0 + bng[i] * 4);
    }

    int cur = 0;
    for (int k0 = 0; k0 < K; k0 += 16) {
#pragma unroll
        for (int i = 0; i < 2; i++) {
            As[cur][akg[i] * 4 + 0][am[i]] = ra[i].x;
            As[cur][akg[i] * 4 + 1][am[i]] = ra[i].y;
            As[cur][akg[i] * 4 + 2][am[i]] = ra[i].z;
            As[cur][akg[i] * 4 + 3][am[i]] = ra[i].w;
            *(float4*)&Bs[cur][bkk[i]][bng[i] * 4] = rb[i];
        }
        __syncthreads();
        if (k0 + 16 < K) {
#pragma unroll
            for (int i = 0; i < 2; i++) {
                ra[i] = *(const float4*)(A + (size_t)(m0 + am[i]) * K + k0 + 16 + akg[i] * 4);
                rb[i] = *(const float4*)(Bm + (size_t)(k0 + 16 + bkk[i]) * N + n0 + bng[i] * 4);
            }
        }
#pragma unroll
        for (int kk = 0; kk < 16; kk++) {
            float4 a0 = *(float4*)&As[cur][kk][ty * 8];
            float4 a1 = *(float4*)&As[cur][kk][ty * 8 + 4];
            float4 b0 = *(float4*)&Bs[cur][kk][tx * 8];
            float4 b1 = *(float4*)&Bs[cur][kk][tx * 8 + 4];
            ull bp0 = pk2(b0.x, b0.y), bp1 = pk2(b0.z, b0.w);
            ull bp2 = pk2(b1.x, b1.y), bp3 = pk2(b1.z, b1.w);
            float av[8] = {a0.x, a0.y, a0.z, a0.w, a1.x, a1.y, a1.z, a1.w};
#pragma unroll
            for (int i = 0; i < 8; i++) {
                ull ad = pk2(av[i], av[i]);
                ffma2(acc[i][0], ad, bp0);
                ffma2(acc[i][1], ad, bp1);
                ffma2(acc[i][2], ad, bp2);
                ffma2(acc[i][3], ad, bp3);
            }
        }
        cur ^= 1;
    }
#pragma unroll
    for (int i = 0; i < 8; i++) {
        int row = m0 + ty * 8 + i;
        float sc = rowscale ? rowscale[row] : 1.f;
        float2 v0 = up2(acc[i][0]), v1 = up2(acc[i][1]);
        float2 v2 = up2(acc[i][2]), v3 = up2(acc[i][3]);
        float4 o0 = make_float4(v0.x * sc, v0.y * sc, v1.x * sc, v1.y * sc);
        float4 o1 = make_float4(v2.x * sc, v2.y * sc, v3.x * sc, v3.y * sc);
        *(float4*)(C + (size_t)row * N + n0 + tx * 8) = o0;
        *(float4*)(C + (size_t)row * N + n0 + tx * 8 + 4) = o1;
    }
}

// ---------------- fused pipeline kernel --------------------------------------
// blockIdx roles:
//   [0, 8)     scan CTAs (one per batch)      — waits on g_flags chunks
//   [8, 40)    norm CTAs (b*4+ks)             — produces g_rnorm + g_nfl
//   [40, 296)  t' CTAs (seq@EW K-split 2)     — produces tp0/tp1 + g_tfl
//   [296, 808) gemm_tn CTAs (K-split 4)       — waits tfl+nfl, produces xq*
#define RF_PAIRS 26
#define SM_PAIRS 6
#define WS2_ELEMS (SM_PAIRS * 2 * 256)           // 3072 ulonglong2 = 48 KB
#define OFF_PART (WS2_ELEMS * 16)
#define OFF_HB (OFF_PART + 4 * 256 * 4)
#define SCAN_SMEM_BYTES (OFF_HB + 2 * 256 * 4)   // 48K + 4K + 2K = 54 KB

__global__ __launch_bounds__(256) void fused_kernel(
    const float* __restrict__ graph, const float* __restrict__ seq,
    const float* __restrict__ ewp,
    const float* __restrict__ Wh, const float* __restrict__ bias,
    float* __restrict__ rn,
    float* __restrict__ tq0, float* __restrict__ tq1,
    float* __restrict__ xq0, float* __restrict__ xq1,
    float* __restrict__ xq2, float* __restrict__ xq3,
    float* __restrict__ out) {
    extern __shared__ unsigned char smraw[];
    const int tid = threadIdx.x;
    const int bid = blockIdx.x;

    if (bid >= 8 && bid < 40) {
        // ================= norm role: rows [ks*256, +256) of batch b ========
        const int nb = bid - 8;
        const int b = nb >> 2, ks4 = nb & 3;
        const int w = tid >> 5, l = tid & 31;
        const float* gb = graph + (size_t)b * L_ * L_ + (size_t)ks4 * 256 * L_;
        for (int r = w; r < 256; r += 8) {
            const float4* row = (const float4*)(gb + (size_t)r * L_);
            float s = 0.f;
#pragma unroll
            for (int i = l; i < L_ / 4; i += 32) {
                float4 v = row[i];
                s += (v.x + v.y) + (v.z + v.w);
            }
#pragma unroll
            for (int o = 16; o; o >>= 1) s += __shfl_xor_sync(0xffffffffu, s, o);
            if (l == 0) rn[b * L_ + ks4 * 256 + r] = 1.f / fmaxf(s, 1e-7f);
        }
        __threadfence();
        __syncthreads();
        if (tid == 0) atomicAdd(&g_nfl[nb], 1);
        return;
    }

    if (bid >= 40 && bid < 296) {
        // ================= t' role: seq @ EW, K-split 2, unscaled ===========
        float (*As)[16][128] = (float (*)[16][128])smraw;
        float (*Bs)[16][128] = (float (*)[16][128])(smraw + 2 * 16 * 128 * 4);
        const int gid = bid - 40;
        const int nt = gid & 1, mt = (gid >> 1) & 63, kz = gid >> 7;
        const int K = 256, N = 256;
        const int m0 = mt * 128, n0 = nt * 128;
        const int kbeg = kz * 128, kend = kbeg + 128;
        float* C = kz ? tq1 : tq0;
        const int tx = tid & 15, ty = tid >> 4;

        ull acc[8][4];
#pragma unroll
        for (int i = 0; i < 8; i++)
#pragma unroll
            for (int j = 0; j < 4; j++) acc[i][j] = 0ull;

        int am[2], akg[2], bkk[2], bng[2];
#pragma unroll
        for (int i = 0; i < 2; i++) {
            int f4 = tid + i * 256;
            am[i] = f4 >> 2; akg[i] = f4 & 3;
            bkk[i] = f4 >> 5; bng[i] = f4 & 31;
        }

        float4 ra[2], rb[2];
#pragma unroll
        for (int i = 0; i < 2; i++) {
            ra[i] = *(const float4*)(seq + (size_t)(m0 + am[i]) * K + kbeg + akg[i] * 4);
            rb[i] = *(const float4*)(ewp + (size_t)(kbeg + bkk[i]) * N + n0 + bng[i] * 4);
        }

        int cur = 0;
        for (int k0 = kbeg; k0 < kend; k0 += 16) {
#pragma unroll
            for (int i = 0; i < 2; i++) {
                As[cur][akg[i] * 4 + 0][am[i]] = ra[i].x;
                As[cur][akg[i] * 4 + 1][am[i]] = ra[i].y;
                As[cur][akg[i] * 4 + 2][am[i]] = ra[i].z;
                As[cur][akg[i] * 4 + 3][am[i]] = ra[i].w;
                *(float4*)&Bs[cur][bkk[i]][bng[i] * 4] = rb[i];
            }
            __syncthreads();
            if (k0 + 16 < kend) {
#pragma unroll
                for (int i = 0; i < 2; i++) {
                    ra[i] = *(const float4*)(seq + (size_t)(m0 + am[i]) * K + k0 + 16 + akg[i] * 4);
                    rb[i] = *(const float4*)(ewp + (size_t)(k0 + 16 + bkk[i]) * N + n0 + bng[i] * 4);
                }
            }
#pragma unroll
            for (int kk = 0; kk < 16; kk++) {
                float4 a0 = *(float4*)&As[cur][kk][ty * 8];
                float4 a1 = *(float4*)&As[cur][kk][ty * 8 + 4];
                float4 b0 = *(float4*)&Bs[cur][kk][tx * 8];
                float4 b1 = *(float4*)&Bs[cur][kk][tx * 8 + 4];
                ull bp0 = pk2(b0.x, b0.y), bp1 = pk2(b0.z, b0.w);
                ull bp2 = pk2(b1.x, b1.y), bp3 = pk2(b1.z, b1.w);
                float av[8] = {a0.x, a0.y, a0.z, a0.w, a1.x, a1.y, a1.z, a1.w};
#pragma unroll
                for (int i = 0; i < 8; i++) {
                    ull ad = pk2(av[i], av[i]);
                    ffma2(acc[i][0], ad, bp0);
                    ffma2(acc[i][1], ad, bp1);
                    ffma2(acc[i][2], ad, bp2);
                    ffma2(acc[i][3], ad, bp3);
                }
            }
            cur ^= 1;
        }
#pragma unroll
        for (int i = 0; i < 8; i++) {
            int row = m0 + ty * 8 + i;
            float2 v0 = up2(acc[i][0]), v1 = up2(acc[i][1]);
            float2 v2 = up2(acc[i][2]), v3 = up2(acc[i][3]);
            float4 o0 = make_float4(v0.x, v0.y, v1.x, v1.y);
            float4 o1 = make_float4(v2.x, v2.y, v3.x, v3.y);
            *(float4*)(C + (size_t)row * N + n0 + tx * 8) = o0;
            *(float4*)(C + (size_t)row * N + n0 + tx * 8 + 4) = o1;
        }
        __threadfence();
        __syncthreads();
        if (tid == 0) atomicAdd(&g_tfl[(mt >> 3) * 4 + ((mt & 7) >> 1)], 1);
        return;
    }

    if (bid >= 296) {
        // ================= gemm_tn role (K-split 4, rn applied to A) ========
        float (*As)[16][128] = (float (*)[16][128])smraw;
        float (*Bs)[16][128] = (float (*)[16][128])(smraw + 2 * 16 * 128 * 4);
        const int gid = bid - 296;
        const int nt = gid & 1, bks = (gid >> 1) & 31, mchunk = gid >> 6;
        const int b = bks >> 2, ks = bks & 3;
        const int kbeg = ks * (L_ / 4), kend = kbeg + (L_ / 4);
        const int N = 256, lda = L_;
        const float* Ab = graph + (size_t)b * L_ * L_;
        const float* Bb0 = tq0 + (size_t)b * L_ * U_;
        const float* Bb1 = tq1 + (size_t)b * L_ * U_;
        const float* rnb = rn + (size_t)b * L_;
        float* Cs = (ks == 0) ? xq0 : (ks == 1) ? xq1 : (ks == 2) ? xq2 : xq3;
        float* C = Cs + (size_t)b * L_ * U_;
        const int m0 = mchunk * 128, n0 = nt * 128;
        const int tx = tid & 15, ty = tid >> 4;

        {
            volatile int* tf = &g_tfl[b * 4 + ks];
            volatile int* nf = &g_nfl[b * 4 + ks];
            if (tid == 0) {
                while (*tf < 8) { }
                while (*nf < 1) { }
            }
            __syncthreads();
            __threadfence();
        }

        ull acc[8][4];
#pragma unroll
        for (int i = 0; i < 8; i++)
#pragma unroll
            for (int j = 0; j < 4; j++) acc[i][j] = 0ull;

        int kk_[2], g_[2];
#pragma unroll
        for (int i = 0; i < 2; i++) {
            int f4 = tid + i * 256;
            kk_[i] = f4 >> 5; g_[i] = f4 & 31;
        }

        float4 ra[2], rb0[2], rb1[2];
        float rsc[2];
#pragma unroll
        for (int i = 0; i < 2; i++) {
            size_t ko = (size_t)(kbeg + kk_[i]);
            ra[i] = *(const float4*)(Ab + ko * lda + m0 + g_[i] * 4);
            rb0[i] = *(const float4*)(Bb0 + ko * N + n0 + g_[i] * 4);
            rb1[i] = *(const float4*)(Bb1 + ko * N + n0 + g_[i] * 4);
            rsc[i] = rnb[ko];
        }

        int cur = 0;
        for (int k0 = kbeg; k0 < kend; k0 += 16) {
#pragma unroll
            for (int i = 0; i < 2; i++) {
                float r = rsc[i];
                float4 sa = make_float4(ra[i].x * r, ra[i].y * r,
                                        ra[i].z * r, ra[i].w * r);
                *(float4*)&As[cur][kk_[i]][g_[i] * 4] = sa;
                float4 s = make_float4(rb0[i].x + rb1[i].x, rb0[i].y + rb1[i].y,
                                       rb0[i].z + rb1[i].z, rb0[i].w + rb1[i].w);
                *(float4*)&Bs[cur][kk_[i]][g_[i] * 4] = s;
            }
            __syncthreads();
            if (k0 + 16 < kend) {
#pragma unroll
                for (int i = 0; i < 2; i++) {
                    size_t ko = (size_t)(k0 + 16 + kk_[i]);
                    ra[i] = *(const float4*)(Ab + ko * lda + m0 + g_[i] * 4);
                    rb0[i] = *(const float4*)(Bb0 + ko * N + n0 + g_[i] * 4);
                    rb1[i] = *(const float4*)(Bb1 + ko * N + n0 + g_[i] * 4);
                    rsc[i] = rnb[ko];
                }
            }
#pragma unroll
            for (int kk = 0; kk < 16; kk++) {
                float4 a0 = *(float4*)&As[cur][kk][ty * 8];
                float4 a1 = *(float4*)&As[cur][kk][ty * 8 + 4];
                float4 b0 = *(float4*)&Bs[cur][kk][tx * 8];
                float4 b1 = *(float4*)&Bs[cur][kk][tx * 8 + 4];
                ull bp0 = pk2(b0.x, b0.y), bp1 = pk2(b0.z, b0.w);
                ull bp2 = pk2(b1.x, b1.y), bp3 = pk2(b1.z, b1.w);
                float av[8] = {a0.x, a0.y, a0.z, a0.w, a1.x, a1.y, a1.z, a1.w};
#pragma unroll
                for (int i = 0; i < 8; i++) {
                    ull ad = pk2(av[i], av[i]);
                    ffma2(acc[i][0], ad, bp0);
                    ffma2(acc[i][1], ad, bp1);
                    ffma2(acc[i][2], ad, bp2);
                    ffma2(acc[i][3], ad, bp3);
                }
            }
            cur ^= 1;
        }
#pragma unroll
        for (int i = 0; i < 8; i++) {
            int row = m0 + ty * 8 + i;
            float2 v0 = up2(acc[i][0]), v1 = up2(acc[i][1]);
            float2 v2 = up2(acc[i][2]), v3 = up2(acc[i][3]);
            float4 o0 = make_float4(v0.x, v0.y, v1.x, v1.y);
            float4 o1 = make_float4(v2.x, v2.y, v3.x, v3.y);
            *(float4*)(C + (size_t)row * N + n0 + tx * 8) = o0;
            *(float4*)(C + (size_t)row * N + n0 + tx * 8 + 4) = o1;
        }
        __threadfence();
        __syncthreads();
        if (tid == 0) atomicAdd(&g_flags[b][mchunk], 1);
        return;
    }

    // ================= scan role (R12-exact: two global barriers/step) ======
    ulonglong2* ws2 = (ulonglong2*)smraw;               // 48 KB weights
    float* part = (float*)(smraw + OFF_PART);           // 4 KB partials
    float* hbuf = (float*)(smraw + OFF_HB);             // 2 KB h (double buf)

    const int b = bid;
    const int w = tid >> 5, l = tid & 31;
    const int ks = w >> 1, oh = w & 1;
    const int u0 = oh * 128 + l * 4;

    for (int idx = tid; idx < WS2_ELEMS; idx += 256) {
        int e = idx >> 8;
        int r = idx & 255;
        int ps = e >> 1, jp = e & 1;
        int wf = r >> 5, lf = r & 31;
        int ksf = wf >> 1, ohf = wf & 1;
        int uf = ohf * 128 + lf * 4 + 2 * jp;
        int kf = ksf * 64 + 2 * (RF_PAIRS + ps);
        ulonglong2 v;
        v.x = pk2(Wh[kf * U_ + uf], Wh[(kf + 1) * U_ + uf]);
        v.y = pk2(Wh[kf * U_ + uf + 1], Wh[(kf + 1) * U_ + uf + 1]);
        ws2[idx] = v;
    }

    ull wreg[4][RF_PAIRS];
#pragma unroll
    for (int j = 0; j < 4; j++)
#pragma unroll
        for (int p = 0; p < RF_PAIRS; p++) {
            int k = ks * 64 + 2 * p;
            wreg[j][p] = pk2(Wh[k * U_ + u0 + j], Wh[(k + 1) * U_ + u0 + j]);
        }

    hbuf[tid] = 0.f;
    hbuf[256 + tid] = 0.f;
    const float bv = bias[tid];
    __syncthreads();

    const float* xp0 = xq0 + (size_t)b * L_ * U_ + tid;
    const float* xp1 = xq1 + (size_t)b * L_ * U_ + tid;
    const float* xp2 = xq2 + (size_t)b * L_ * U_ + tid;
    const float* xp3 = xq3 + (size_t)b * L_ * U_ + tid;
    float* op = out + (size_t)b * L_ * U_ + tid;
    int cur = 0;

    const ulonglong2* wp = ws2 + tid;
    volatile int* flagp = &g_flags[b][0];

    for (int c = 0; c < NCHUNK; c++) {
        if (tid == 0) {
            while (flagp[c] < 8) { }
        }
        __syncthreads();
        __threadfence();  // acquire: pair with producers' release fences

        for (int si = 0; si < CHUNK; si++) {
            int s = c * CHUNK + si;
            size_t xo = (size_t)s * U_;
            float xa = xp0[xo], xb = xp1[xo], xc = xp2[xo], xd = xp3[xo];

            const ulonglong2* hp2 = (const ulonglong2*)(hbuf + cur * 256 + ks * 64);
            ull a0 = 0ull, a1 = 0ull, a2 = 0ull, a3 = 0ull;
            // SMEM-weight FMAs first (R9 win), LDS.128 packed (R12)
#pragma unroll
            for (int qq = 0; qq < 3; qq++) { // pairs 26..31
                ulonglong2 hv = hp2[13 + qq];
                int ps0 = 2 * qq, ps1 = 2 * qq + 1;
                ulonglong2 W0a = wp[(ps0 * 2 + 0) * 256];
                ulonglong2 W0b = wp[(ps0 * 2 + 1) * 256];
                ffma2(a0, hv.x, W0a.x);
                ffma2(a1, hv.x, W0a.y);
                ffma2(a2, hv.x, W0b.x);
                ffma2(a3, hv.x, W0b.y);
                ulonglong2 W1a = wp[(ps1 * 2 + 0) * 256];
                ulonglong2 W1b = wp[(ps1 * 2 + 1) * 256];
                ffma2(a0, hv.y, W1a.x);
                ffma2(a1, hv.y, W1a.y);
                ffma2(a2, hv.y, W1b.x);
                ffma2(a3, hv.y, W1b.y);
            }
#pragma unroll
            for (int q = 0; q < 13; q++) {   // pairs 0..25 (RF)
                ulonglong2 hv = hp2[q];
                ffma2(a0, hv.x, wreg[0][2 * q]);
                ffma2(a1, hv.x, wreg[1][2 * q]);
                ffma2(a2, hv.x, wreg[2][2 * q]);
                ffma2(a3, hv.x, wreg[3][2 * q]);
                ffma2(a0, hv.y, wreg[0][2 * q + 1]);
                ffma2(a1, hv.y, wreg[1][2 * q + 1]);
                ffma2(a2, hv.y, wreg[2][2 * q + 1]);
                ffma2(a3, hv.y, wreg[3][2 * q + 1]);
            }
            float2 v0 = up2(a0), v1 = up2(a1), v2 = up2(a2), v3 = up2(a3);
            float4 pr = make_float4(v0.x + v0.y, v1.x + v1.y,
                                    v2.x + v2.y, v3.x + v3.y);
            float xv = ((xa + xb) + (xc + xd)) + bv;
            *(float4*)&part[ks * 256 + u0] = pr;
            __syncthreads();

            float z = part[tid] + part[256 + tid] + part[512 + tid] +
                      part[768 + tid] + xv;
            float h = fast_tanh(z);
            hbuf[(cur ^ 1) * 256 + tid] = h;
            op[xo] = h;
            cur ^= 1;
            __syncthreads();
        }
    }
}

// ---------------- launch --------------------------------------------------
extern "C" void kernel_launch(void* const* d_in, const int* in_sizes, int n_in,
                              void* d_out, int out_size) {
    const float* seq = (const float*)d_in[0];    // (8,1024,256)
    const float* graph = (const float*)d_in[1];  // (8,1024,1024)
    const float* E = (const float*)d_in[2];      // (256,256)
    const float* Wx = (const float*)d_in[3];     // (256,256)
    const float* Wh = (const float*)d_in[4];     // (256,256)
    const float* bias = (const float*)d_in[5];   // (256,)
    float* out = (float*)d_out;                  // (8,1024,256)

    float *ew, *rn, *t0, *t1, *x0, *x1, *x2, *x3;
    cudaGetSymbolAddress((void**)&ew, g_EW);
    cudaGetSymbolAddress((void**)&rn, g_rnorm);
    cudaGetSymbolAddress((void**)&t0, g_tp0);
    cudaGetSymbolAddress((void**)&t1, g_tp1);
    cudaGetSymbolAddress((void**)&x0, g_xp0);
    cudaGetSymbolAddress((void**)&x1, g_xp1);
    cudaGetSymbolAddress((void**)&x2, g_xp2);
    cudaGetSymbolAddress((void**)&x3, g_xp3);

    // EW = E @ Wx (also zeroes all pipeline flags in block (0,0))
    gemm_nn<<<dim3(2, 2), 256>>>(E, Wx, ew, 256, nullptr);
    // everything else: one fused pipeline kernel
    cudaFuncSetAttribute(fused_kernel, cudaFuncAttributeMaxDynamicSharedMemorySize,
                         SCAN_SMEM_BYTES);
    fused_kernel<<<808, 256, SCAN_SMEM_BYTES>>>(graph, seq, ew, Wh, bias, rn,
                                                t0, t1, x0, x1, x2, x3, out);
}

// round 17
// speedup vs baseline: 1.2933x; 1.0290x over previous
#include <cuda_runtime.h>
#include <cuda_fp16.h>
#include <math.h>

#define B_ 8
#define L_ 1024
#define D_ 256
#define U_ 256
#define NCHUNK 8
#define CHUNK 128

typedef unsigned long long ull;

// ---------------- scratch (device globals; no allocation allowed) ----------
__device__ float g_EW[D_ * U_];          // E @ Wx            (256 KB)
__device__ float g_rnorm[B_ * L_];       // 1/max(rowsum,eps)
__device__ float g_tp0[B_ * L_ * U_];    // seq[:,0:128]@EW[0:128]   (unscaled)
__device__ float g_tp1[B_ * L_ * U_];    // seq[:,128:256]@EW[128:256]
__device__ float g_xp0[B_ * L_ * U_];    // G^T @ t partials  (8 MB each)
__device__ float g_xp1[B_ * L_ * U_];
__device__ float g_xp2[B_ * L_ * U_];
__device__ float g_xp3[B_ * L_ * U_];
__device__ int g_flags[B_][NCHUNK];      // xproj chunk flags (count 8)
__device__ int g_tfl[B_ * 4];            // t ready per (b,ks) (count 8)
__device__ int g_nfl[B_ * 4];            // rn ready per (b,ks) (count 1)

// ---------------- packed f32x2 helpers (sm_103a) ----------------------------
__device__ __forceinline__ ull pk2(float lo, float hi) {
    ull r; asm("mov.b64 %0,{%1,%2};" : "=l"(r) : "f"(lo), "f"(hi)); return r;
}
__device__ __forceinline__ void ffma2(ull& d, ull a, ull b) {
    asm("fma.rn.f32x2 %0,%1,%2,%0;" : "+l"(d) : "l"(a), "l"(b));
}
__device__ __forceinline__ float2 up2(ull a) {
    float lo, hi; asm("mov.b64 {%0,%1},%2;" : "=f"(lo), "=f"(hi) : "l"(a));
    float2 r; r.x = lo; r.y = hi; return r;
}
// tanh(z) = 1 - 2/(1+exp(2z)) via MUFU (rel err ~1e-6; validated R3-R14)
__device__ __forceinline__ float fast_tanh(float z) {
    float t2 = z * 2.885390081777927f;  // 2*log2(e)
    float ex; asm("ex2.approx.f32 %0,%1;" : "=f"(ex) : "f"(t2));
    float den = ex + 1.0f;
    float rc; asm("rcp.approx.f32 %0,%1;" : "=f"(rc) : "f"(den));
    return fmaf(-2.0f, rc, 1.0f);
}
// half2 (w_k, w_k+1) -> f32x2 ull, fp32 compute path
__device__ __forceinline__ ull h2w(unsigned int h) {
    float2 f = __half22float2(*(__half2*)&h);
    return pk2(f.x, f.y);
}

// ---------------- 1) GEMM NN standalone (EW = E @ Wx; also zeroes flags) ----
__global__ __launch_bounds__(256) void gemm_nn(const float* __restrict__ A,
                                               const float* __restrict__ Bm,
                                               float* __restrict__ C, int K,
                                               const float* __restrict__ rowscale) {
    __shared__ float As[2][16][128];
    __shared__ float Bs[2][16][128];
    const int N = 256;
    const int m0 = blockIdx.y * 128, n0 = blockIdx.x * 128;
    const int t = threadIdx.x;
    const int tx = t & 15, ty = t >> 4;

    // flag zeroing piggybacked on block (0,0): same-stream kernels serialize,
    // so all flags are zero before fused_kernel starts (every graph replay).
    if (blockIdx.x == 0 && blockIdx.y == 0) {
        if (t < B_ * NCHUNK) ((int*)g_flags)[t] = 0;
        if (t < B_ * 4) { g_tfl[t] = 0; g_nfl[t] = 0; }
    }

    ull acc[8][4];
#pragma unroll
    for (int i = 0; i < 8; i++)
#pragma unroll
        for (int j = 0; j < 4; j++) acc[i][j] = 0ull;

    int am[2], akg[2], bkk[2], bng[2];
#pragma unroll
    for (int i = 0; i < 2; i++) {
        int f4 = t + i * 256;
        am[i] = f4 >> 2; akg[i] = f4 & 3;
        bkk[i] = f4 >> 5; bng[i] = f4 & 31;
    }

    float4 ra[2], rb[2];
#pragma unroll
    for (int i = 0; i < 2; i++) {
        ra[i] = *(const float4*)(A + (size_t)(m0 + am[i]) * K + akg[i] * 4);
        rb[i] = *(const float4*)(Bm + (size_t)bkk[i] * N + n0 + bng[i] * 4);
    }

    int cur = 0;
    for (int k0 = 0; k0 < K; k0 += 16) {
#pragma unroll
        for (int i = 0; i < 2; i++) {
            As[cur][akg[i] * 4 + 0][am[i]] = ra[i].x;
            As[cur][akg[i] * 4 + 1][am[i]] = ra[i].y;
            As[cur][akg[i] * 4 + 2][am[i]] = ra[i].z;
            As[cur][akg[i] * 4 + 3][am[i]] = ra[i].w;
            *(float4*)&Bs[cur][bkk[i]][bng[i] * 4] = rb[i];
        }
        __syncthreads();
        if (k0 + 16 < K) {
#pragma unroll
            for (int i = 0; i < 2; i++) {
                ra[i] = *(const float4*)(A + (size_t)(m0 + am[i]) * K + k0 + 16 + akg[i] * 4);
                rb[i] = *(const float4*)(Bm + (size_t)(k0 + 16 + bkk[i]) * N + n0 + bng[i] * 4);
            }
        }
#pragma unroll
        for (int kk = 0; kk < 16; kk++) {
            float4 a0 = *(float4*)&As[cur][kk][ty * 8];
            float4 a1 = *(float4*)&As[cur][kk][ty * 8 + 4];
            float4 b0 = *(float4*)&Bs[cur][kk][tx * 8];
            float4 b1 = *(float4*)&Bs[cur][kk][tx * 8 + 4];
            ull bp0 = pk2(b0.x, b0.y), bp1 = pk2(b0.z, b0.w);
            ull bp2 = pk2(b1.x, b1.y), bp3 = pk2(b1.z, b1.w);
            float av[8] = {a0.x, a0.y, a0.z, a0.w, a1.x, a1.y, a1.z, a1.w};
#pragma unroll
            for (int i = 0; i < 8; i++) {
                ull ad = pk2(av[i], av[i]);
                ffma2(acc[i][0], ad, bp0);
                ffma2(acc[i][1], ad, bp1);
                ffma2(acc[i][2], ad, bp2);
                ffma2(acc[i][3], ad, bp3);
            }
        }
        cur ^= 1;
    }
#pragma unroll
    for (int i = 0; i < 8; i++) {
        int row = m0 + ty * 8 + i;
        float sc = rowscale ? rowscale[row] : 1.f;
        float2 v0 = up2(acc[i][0]), v1 = up2(acc[i][1]);
        float2 v2 = up2(acc[i][2]), v3 = up2(acc[i][3]);
        float4 o0 = make_float4(v0.x * sc, v0.y * sc, v1.x * sc, v1.y * sc);
        float4 o1 = make_float4(v2.x * sc, v2.y * sc, v3.x * sc, v3.y * sc);
        *(float4*)(C + (size_t)row * N + n0 + tx * 8) = o0;
        *(float4*)(C + (size_t)row * N + n0 + tx * 8 + 4) = o1;
    }
}

// ---------------- fused pipeline kernel --------------------------------------
// blockIdx roles:
//   [0, 8)     scan CTAs (one per batch)      — waits on g_flags chunks
//   [8, 40)    norm CTAs (b*4+ks)             — produces g_rnorm + g_nfl
//   [40, 296)  t' CTAs (seq@EW K-split 2)     — produces tp0/tp1 + g_tfl
//   [296, 808) gemm_tn CTAs (K-split 4)       — waits tfl+nfl, produces xq*
#define RF_PAIRS 26
#define SM_PAIRS 6
#define WSH_ELEMS (SM_PAIRS * 256)               // uint4 count: 1536 = 24 KB
#define OFF_PART (WSH_ELEMS * 16)
#define OFF_HB (OFF_PART + 4 * 256 * 4)
#define SCAN_USED_BYTES (OFF_HB + 2 * 256 * 4)   // 24K + 4K + 2K = 30 KB
// GEMM roles carve As+Bs = 32 KB out of smraw; dynamic SMEM = max over roles.
#define GEMM_SMEM_BYTES (2 * 2 * 16 * 128 * 4)   // 32 KB
#define FUSED_SMEM_BYTES (GEMM_SMEM_BYTES > SCAN_USED_BYTES ? GEMM_SMEM_BYTES \
                                                            : SCAN_USED_BYTES)

__global__ __launch_bounds__(256) void fused_kernel(
    const float* __restrict__ graph, const float* __restrict__ seq,
    const float* __restrict__ ewp,
    const float* __restrict__ Wh, const float* __restrict__ bias,
    float* __restrict__ rn,
    float* __restrict__ tq0, float* __restrict__ tq1,
    float* __restrict__ xq0, float* __restrict__ xq1,
    float* __restrict__ xq2, float* __restrict__ xq3,
    float* __restrict__ out) {
    extern __shared__ unsigned char smraw[];
    const int tid = threadIdx.x;
    const int bid = blockIdx.x;

    if (bid >= 8 && bid < 40) {
        // ================= norm role: rows [ks*256, +256) of batch b ========
        const int nb = bid - 8;
        const int b = nb >> 2, ks4 = nb & 3;
        const int w = tid >> 5, l = tid & 31;
        const float* gb = graph + (size_t)b * L_ * L_ + (size_t)ks4 * 256 * L_;
        for (int r = w; r < 256; r += 8) {
            const float4* row = (const float4*)(gb + (size_t)r * L_);
            float s = 0.f;
#pragma unroll
            for (int i = l; i < L_ / 4; i += 32) {
                float4 v = row[i];
                s += (v.x + v.y) + (v.z + v.w);
            }
#pragma unroll
            for (int o = 16; o; o >>= 1) s += __shfl_xor_sync(0xffffffffu, s, o);
            if (l == 0) rn[b * L_ + ks4 * 256 + r] = 1.f / fmaxf(s, 1e-7f);
        }
        __threadfence();
        __syncthreads();
        if (tid == 0) atomicAdd(&g_nfl[nb], 1);
        return;
    }

    if (bid >= 40 && bid < 296) {
        // ================= t' role: seq @ EW, K-split 2, unscaled ===========
        float (*As)[16][128] = (float (*)[16][128])smraw;
        float (*Bs)[16][128] = (float (*)[16][128])(smraw + 2 * 16 * 128 * 4);
        const int gid = bid - 40;
        const int nt = gid & 1, mt = (gid >> 1) & 63, kz = gid >> 7;
        const int K = 256, N = 256;
        const int m0 = mt * 128, n0 = nt * 128;
        const int kbeg = kz * 128, kend = kbeg + 128;
        float* C = kz ? tq1 : tq0;
        const int tx = tid & 15, ty = tid >> 4;

        ull acc[8][4];
#pragma unroll
        for (int i = 0; i < 8; i++)
#pragma unroll
            for (int j = 0; j < 4; j++) acc[i][j] = 0ull;

        int am[2], akg[2], bkk[2], bng[2];
#pragma unroll
        for (int i = 0; i < 2; i++) {
            int f4 = tid + i * 256;
            am[i] = f4 >> 2; akg[i] = f4 & 3;
            bkk[i] = f4 >> 5; bng[i] = f4 & 31;
        }

        float4 ra[2], rb[2];
#pragma unroll
        for (int i = 0; i < 2; i++) {
            ra[i] = *(const float4*)(seq + (size_t)(m0 + am[i]) * K + kbeg + akg[i] * 4);
            rb[i] = *(const float4*)(ewp + (size_t)(kbeg + bkk[i]) * N + n0 + bng[i] * 4);
        }

        int cur = 0;
        for (int k0 = kbeg; k0 < kend; k0 += 16) {
#pragma unroll
            for (int i = 0; i < 2; i++) {
                As[cur][akg[i] * 4 + 0][am[i]] = ra[i].x;
                As[cur][akg[i] * 4 + 1][am[i]] = ra[i].y;
                As[cur][akg[i] * 4 + 2][am[i]] = ra[i].z;
                As[cur][akg[i] * 4 + 3][am[i]] = ra[i].w;
                *(float4*)&Bs[cur][bkk[i]][bng[i] * 4] = rb[i];
            }
            __syncthreads();
            if (k0 + 16 < kend) {
#pragma unroll
                for (int i = 0; i < 2; i++) {
                    ra[i] = *(const float4*)(seq + (size_t)(m0 + am[i]) * K + k0 + 16 + akg[i] * 4);
                    rb[i] = *(const float4*)(ewp + (size_t)(k0 + 16 + bkk[i]) * N + n0 + bng[i] * 4);
                }
            }
#pragma unroll
            for (int kk = 0; kk < 16; kk++) {
                float4 a0 = *(float4*)&As[cur][kk][ty * 8];
                float4 a1 = *(float4*)&As[cur][kk][ty * 8 + 4];
                float4 b0 = *(float4*)&Bs[cur][kk][tx * 8];
                float4 b1 = *(float4*)&Bs[cur][kk][tx * 8 + 4];
                ull bp0 = pk2(b0.x, b0.y), bp1 = pk2(b0.z, b0.w);
                ull bp2 = pk2(b1.x, b1.y), bp3 = pk2(b1.z, b1.w);
                float av[8] = {a0.x, a0.y, a0.z, a0.w, a1.x, a1.y, a1.z, a1.w};
#pragma unroll
                for (int i = 0; i < 8; i++) {
                    ull ad = pk2(av[i], av[i]);
                    ffma2(acc[i][0], ad, bp0);
                    ffma2(acc[i][1], ad, bp1);
                    ffma2(acc[i][2], ad, bp2);
                    ffma2(acc[i][3], ad, bp3);
                }
            }
            cur ^= 1;
        }
#pragma unroll
        for (int i = 0; i < 8; i++) {
            int row = m0 + ty * 8 + i;
            float2 v0 = up2(acc[i][0]), v1 = up2(acc[i][1]);
            float2 v2 = up2(acc[i][2]), v3 = up2(acc[i][3]);
            float4 o0 = make_float4(v0.x, v0.y, v1.x, v1.y);
            float4 o1 = make_float4(v2.x, v2.y, v3.x, v3.y);
            *(float4*)(C + (size_t)row * N + n0 + tx * 8) = o0;
            *(float4*)(C + (size_t)row * N + n0 + tx * 8 + 4) = o1;
        }
        __threadfence();
        __syncthreads();
        if (tid == 0) atomicAdd(&g_tfl[(mt >> 3) * 4 + ((mt & 7) >> 1)], 1);
        return;
    }

    if (bid >= 296) {
        // ================= gemm_tn role (K-split 4, rn applied to A) ========
        float (*As)[16][128] = (float (*)[16][128])smraw;
        float (*Bs)[16][128] = (float (*)[16][128])(smraw + 2 * 16 * 128 * 4);
        const int gid = bid - 296;
        const int nt = gid & 1, bks = (gid >> 1) & 31, mchunk = gid >> 6;
        const int b = bks >> 2, ks = bks & 3;
        const int kbeg = ks * (L_ / 4), kend = kbeg + (L_ / 4);
        const int N = 256, lda = L_;
        const float* Ab = graph + (size_t)b * L_ * L_;
        const float* Bb0 = tq0 + (size_t)b * L_ * U_;
        const float* Bb1 = tq1 + (size_t)b * L_ * U_;
        const float* rnb = rn + (size_t)b * L_;
        float* Cs = (ks == 0) ? xq0 : (ks == 1) ? xq1 : (ks == 2) ? xq2 : xq3;
        float* C = Cs + (size_t)b * L_ * U_;
        const int m0 = mchunk * 128, n0 = nt * 128;
        const int tx = tid & 15, ty = tid >> 4;

        {
            volatile int* tf = &g_tfl[b * 4 + ks];
            volatile int* nf = &g_nfl[b * 4 + ks];
            if (tid == 0) {
                while (*tf < 8) { }
                while (*nf < 1) { }
            }
            __syncthreads();
            __threadfence();
        }

        ull acc[8][4];
#pragma unroll
        for (int i = 0; i < 8; i++)
#pragma unroll
            for (int j = 0; j < 4; j++) acc[i][j] = 0ull;

        int kk_[2], g_[2];
#pragma unroll
        for (int i = 0; i < 2; i++) {
            int f4 = tid + i * 256;
            kk_[i] = f4 >> 5; g_[i] = f4 & 31;
        }

        float4 ra[2], rb0[2], rb1[2];
        float rsc[2];
#pragma unroll
        for (int i = 0; i < 2; i++) {
            size_t ko = (size_t)(kbeg + kk_[i]);
            ra[i] = *(const float4*)(Ab + ko * lda + m0 + g_[i] * 4);
            rb0[i] = *(const float4*)(Bb0 + ko * N + n0 + g_[i] * 4);
            rb1[i] = *(const float4*)(Bb1 + ko * N + n0 + g_[i] * 4);
            rsc[i] = rnb[ko];
        }

        int cur = 0;
        for (int k0 = kbeg; k0 < kend; k0 += 16) {
#pragma unroll
            for (int i = 0; i < 2; i++) {
                float r = rsc[i];
                float4 sa = make_float4(ra[i].x * r, ra[i].y * r,
                                        ra[i].z * r, ra[i].w * r);
                *(float4*)&As[cur][kk_[i]][g_[i] * 4] = sa;
                float4 s = make_float4(rb0[i].x + rb1[i].x, rb0[i].y + rb1[i].y,
                                       rb0[i].z + rb1[i].z, rb0[i].w + rb1[i].w);
                *(float4*)&Bs[cur][kk_[i]][g_[i] * 4] = s;
            }
            __syncthreads();
            if (k0 + 16 < kend) {
#pragma unroll
                for (int i = 0; i < 2; i++) {
                    size_t ko = (size_t)(k0 + 16 + kk_[i]);
                    ra[i] = *(const float4*)(Ab + ko * lda + m0 + g_[i] * 4);
                    rb0[i] = *(const float4*)(Bb0 + ko * N + n0 + g_[i] * 4);
                    rb1[i] = *(const float4*)(Bb1 + ko * N + n0 + g_[i] * 4);
                    rsc[i] = rnb[ko];
                }
            }
#pragma unroll
            for (int kk = 0; kk < 16; kk++) {
                float4 a0 = *(float4*)&As[cur][kk][ty * 8];
                float4 a1 = *(float4*)&As[cur][kk][ty * 8 + 4];
                float4 b0 = *(float4*)&Bs[cur][kk][tx * 8];
                float4 b1 = *(float4*)&Bs[cur][kk][tx * 8 + 4];
                ull bp0 = pk2(b0.x, b0.y), bp1 = pk2(b0.z, b0.w);
                ull bp2 = pk2(b1.x, b1.y), bp3 = pk2(b1.z, b1.w);
                float av[8] = {a0.x, a0.y, a0.z, a0.w, a1.x, a1.y, a1.z, a1.w};
#pragma unroll
                for (int i = 0; i < 8; i++) {
                    ull ad = pk2(av[i], av[i]);
                    ffma2(acc[i][0], ad, bp0);
                    ffma2(acc[i][1], ad, bp1);
                    ffma2(acc[i][2], ad, bp2);
                    ffma2(acc[i][3], ad, bp3);
                }
            }
            cur ^= 1;
        }
#pragma unroll
        for (int i = 0; i < 8; i++) {
            int row = m0 + ty * 8 + i;
            float2 v0 = up2(acc[i][0]), v1 = up2(acc[i][1]);
            float2 v2 = up2(acc[i][2]), v3 = up2(acc[i][3]);
            float4 o0 = make_float4(v0.x, v0.y, v1.x, v1.y);
            float4 o1 = make_float4(v2.x, v2.y, v3.x, v3.y);
            *(float4*)(C + (size_t)row * N + n0 + tx * 8) = o0;
            *(float4*)(C + (size_t)row * N + n0 + tx * 8 + 4) = o1;
        }
        __threadfence();
        __syncthreads();
        if (tid == 0) atomicAdd(&g_flags[b][mchunk], 1);
        return;
    }

    // ===== scan role: fp16 SMEM weight STORAGE, fp32 COMPUTE (R16 fix) ======
    uint4* wsH = (uint4*)smraw;                         // 24 KB fp16 weights
    float* part = (float*)(smraw + OFF_PART);           // 4 KB partials
    float* hbuf = (float*)(smraw + OFF_HB);             // 2 KB h (double buf)

    const int b = bid;
    const int w = tid >> 5, l = tid & 31;
    const int ks = w >> 1, oh = w & 1;
    const int u0 = oh * 128 + l * 4;

    // wsH[ps*256 + owner] = 4x half2{ W[kf][u0+j], W[kf+1][u0+j] }, j=0..3,
    // kf = ks*64 + 2*(RF_PAIRS+ps) for the owning thread's (ks, u0).
    for (int idx = tid; idx < WSH_ELEMS; idx += 256) {
        int ps = idx >> 8;
        int r = idx & 255;
        int wf = r >> 5, lf = r & 31;
        int ksf = wf >> 1, ohf = wf & 1;
        int uf = ohf * 128 + lf * 4;
        int kf = ksf * 64 + 2 * (RF_PAIRS + ps);
        uint4 v;
        __half2 h0 = __floats2half2_rn(Wh[kf * U_ + uf + 0], Wh[(kf + 1) * U_ + uf + 0]);
        __half2 h1 = __floats2half2_rn(Wh[kf * U_ + uf + 1], Wh[(kf + 1) * U_ + uf + 1]);
        __half2 h2 = __floats2half2_rn(Wh[kf * U_ + uf + 2], Wh[(kf + 1) * U_ + uf + 2]);
        __half2 h3 = __floats2half2_rn(Wh[kf * U_ + uf + 3], Wh[(kf + 1) * U_ + uf + 3]);
        v.x = *(unsigned int*)&h0;
        v.y = *(unsigned int*)&h1;
        v.z = *(unsigned int*)&h2;
        v.w = *(unsigned int*)&h3;
        wsH[idx] = v;
    }

    ull wreg[4][RF_PAIRS];
#pragma unroll
    for (int j = 0; j < 4; j++)
#pragma unroll
        for (int p = 0; p < RF_PAIRS; p++) {
            int k = ks * 64 + 2 * p;
            wreg[j][p] = pk2(Wh[k * U_ + u0 + j], Wh[(k + 1) * U_ + u0 + j]);
        }

    hbuf[tid] = 0.f;
    hbuf[256 + tid] = 0.f;
    const float bv = bias[tid];
    __syncthreads();

    const float* xp0 = xq0 + (size_t)b * L_ * U_ + tid;
    const float* xp1 = xq1 + (size_t)b * L_ * U_ + tid;
    const float* xp2 = xq2 + (size_t)b * L_ * U_ + tid;
    const float* xp3 = xq3 + (size_t)b * L_ * U_ + tid;
    float* op = out + (size_t)b * L_ * U_ + tid;
    int cur = 0;

    const uint4* wHp = wsH + tid;        // stride 256 per ps
    volatile int* flagp = &g_flags[b][0];

    for (int c = 0; c < NCHUNK; c++) {
        if (tid == 0) {
            while (flagp[c] < 8) { }
        }
        __syncthreads();
        __threadfence();  // acquire: pair with producers' release fences

        for (int si = 0; si < CHUNK; si++) {
            int s = c * CHUNK + si;
            size_t xo = (size_t)s * U_;
            float xa = xp0[xo], xb = xp1[xo], xc = xp2[xo], xd = xp3[xo];

            const ulonglong2* hp2 = (const ulonglong2*)(hbuf + cur * 256 + ks * 64);
            ull a0 = 0ull, a1 = 0ull, a2 = 0ull, a3 = 0ull;

            // SMEM-weight section FIRST: fp16 storage -> fp32 ffma2 compute.
#pragma unroll
            for (int qq = 0; qq < 3; qq++) { // pairs 26..31
                ulonglong2 hv = hp2[13 + qq];
                uint4 W0 = wHp[(2 * qq) * 256];
                ffma2(a0, hv.x, h2w(W0.x));
                ffma2(a1, hv.x, h2w(W0.y));
                ffma2(a2, hv.x, h2w(W0.z));
                ffma2(a3, hv.x, h2w(W0.w));
                uint4 W1 = wHp[(2 * qq + 1) * 256];
                ffma2(a0, hv.y, h2w(W1.x));
                ffma2(a1, hv.y, h2w(W1.y));
                ffma2(a2, hv.y, h2w(W1.z));
                ffma2(a3, hv.y, h2w(W1.w));
            }
#pragma unroll
            for (int q = 0; q < 13; q++) {   // pairs 0..25 (RF, fp32)
                ulonglong2 hv = hp2[q];
                ffma2(a0, hv.x, wreg[0][2 * q]);
                ffma2(a1, hv.x, wreg[1][2 * q]);
                ffma2(a2, hv.x, wreg[2][2 * q]);
                ffma2(a3, hv.x, wreg[3][2 * q]);
                ffma2(a0, hv.y, wreg[0][2 * q + 1]);
                ffma2(a1, hv.y, wreg[1][2 * q + 1]);
                ffma2(a2, hv.y, wreg[2][2 * q + 1]);
                ffma2(a3, hv.y, wreg[3][2 * q + 1]);
            }
            float2 v0 = up2(a0), v1 = up2(a1), v2 = up2(a2), v3 = up2(a3);
            float4 pr = make_float4(v0.x + v0.y, v1.x + v1.y,
                                    v2.x + v2.y, v3.x + v3.y);
            float xv = ((xa + xb) + (xc + xd)) + bv;
            *(float4*)&part[ks * 256 + u0] = pr;
            __syncthreads();

            float z = part[tid] + part[256 + tid] + part[512 + tid] +
                      part[768 + tid] + xv;
            float h = fast_tanh(z);
            hbuf[(cur ^ 1) * 256 + tid] = h;
            op[xo] = h;
            cur ^= 1;
            __syncthreads();
        }
    }
}

// ---------------- launch --------------------------------------------------
extern "C" void kernel_launch(void* const* d_in, const int* in_sizes, int n_in,
                              void* d_out, int out_size) {
    const float* seq = (const float*)d_in[0];    // (8,1024,256)
    const float* graph = (const float*)d_in[1];  // (8,1024,1024)
    const float* E = (const float*)d_in[2];      // (256,256)
    const float* Wx = (const float*)d_in[3];     // (256,256)
    const float* Wh = (const float*)d_in[4];     // (256,256)
    const float* bias = (const float*)d_in[5];   // (256,)
    float* out = (float*)d_out;                  // (8,1024,256)

    float *ew, *rn, *t0, *t1, *x0, *x1, *x2, *x3;
    cudaGetSymbolAddress((void**)&ew, g_EW);
    cudaGetSymbolAddress((void**)&rn, g_rnorm);
    cudaGetSymbolAddress((void**)&t0, g_tp0);
    cudaGetSymbolAddress((void**)&t1, g_tp1);
    cudaGetSymbolAddress((void**)&x0, g_xp0);
    cudaGetSymbolAddress((void**)&x1, g_xp1);
    cudaGetSymbolAddress((void**)&x2, g_xp2);
    cudaGetSymbolAddress((void**)&x3, g_xp3);

    // EW = E @ Wx (also zeroes all pipeline flags in block (0,0))
    gemm_nn<<<dim3(2, 2), 256>>>(E, Wx, ew, 256, nullptr);
    // everything else: one fused pipeline kernel
    cudaFuncSetAttribute(fused_kernel, cudaFuncAttributeMaxDynamicSharedMemorySize,
                         FUSED_SMEM_BYTES);
    fused_kernel<<<808, 256, FUSED_SMEM_BYTES>>>(graph, seq, ew, Wh, bias, rn,
                                                 t0, t1, x0, x1, x2, x3, out);
}